// round 3
// baseline (speedup 1.0000x reference)
#include <cuda_runtime.h>
#include <math.h>

// Problem constants (fixed by reference: H = W = 2048)
#define H_ 2048
#define W_ 2048
#define HW_ (H_ * W_)
#define LOG2W 11

// Scratch for horizontal gaussian pass: 3 * 4M floats = 48 MB
__device__ float g_tmp[3 * HW_];

// ---------------------------------------------------------------------------
// Kernel 1: horizontal 1x5 gaussian (zero pad 2). Ascending-FMA accumulation,
// border taps as explicit zeros (bit-identical to including w*0 terms).
// ---------------------------------------------------------------------------
__global__ void blur_h_k(const float* __restrict__ img, const float* __restrict__ g) {
    int idx = blockIdx.x * blockDim.x + threadIdx.x;
    if (idx >= 3 * HW_) return;
    int x = idx & (W_ - 1);
    const float* row = img + (idx - x);
    float x0 = (x >= 2)     ? row[x - 2] : 0.f;
    float x1 = (x >= 1)     ? row[x - 1] : 0.f;
    float x2 =                row[x];
    float x3 = (x + 1 < W_) ? row[x + 1] : 0.f;
    float x4 = (x + 2 < W_) ? row[x + 2] : 0.f;
    float acc = __fmul_rn(g[0], x0);
    acc = fmaf(g[1], x1, acc);
    acc = fmaf(g[2], x2, acc);
    acc = fmaf(g[3], x3, acc);
    acc = fmaf(g[4], x4, acc);
    g_tmp[idx] = acc;
}

// ---------------------------------------------------------------------------
// Kernel 2: vertical 5x1 gaussian (zero pad 2) -> blurred. Same FMA chain.
// ---------------------------------------------------------------------------
__global__ void blur_v_k(const float* __restrict__ g, float* __restrict__ blurred) {
    int idx = blockIdx.x * blockDim.x + threadIdx.x;
    if (idx >= 3 * HW_) return;
    int y = (idx >> LOG2W) & (H_ - 1);
    float x0 = (y >= 2)     ? g_tmp[idx - 2 * W_] : 0.f;
    float x1 = (y >= 1)     ? g_tmp[idx - W_]     : 0.f;
    float x2 =                g_tmp[idx];
    float x3 = (y + 1 < H_) ? g_tmp[idx + W_]     : 0.f;
    float x4 = (y + 2 < H_) ? g_tmp[idx + 2 * W_] : 0.f;
    float acc = __fmul_rn(g[0], x0);
    acc = fmaf(g[1], x1, acc);
    acc = fmaf(g[2], x2, acc);
    acc = fmaf(g[3], x3, acc);
    acc = fmaf(g[4], x4, acc);
    blurred[idx] = acc;
}

// ---------------------------------------------------------------------------
// Kernel 3: Sobel per channel (zero pad 1, ascending row-major FMA chains),
// grad_mag, orient via exact f32 emulation of the reference pipeline
// (atan2f == libdevice __nv_atan2f == XLA's arctan2), early_threshold.
// ---------------------------------------------------------------------------
__global__ void sobel_k(const float* __restrict__ blurred,
                        const float* __restrict__ thr_p,
                        float* __restrict__ grad,
                        float* __restrict__ orient,
                        float* __restrict__ early) {
    int idx = blockIdx.x * blockDim.x + threadIdx.x;
    if (idx >= HW_) return;
    int x = idx & (W_ - 1);
    int y = idx >> LOG2W;
    bool xm = (x > 0), xp = (x < W_ - 1);
    bool ym = (y > 0), yp = (y < H_ - 1);

    float mag = 0.f, sx = 0.f, sy = 0.f;
#pragma unroll
    for (int c = 0; c < 3; ++c) {
        const float* b = blurred + c * HW_ + idx;
        float a00 = (ym && xm) ? b[-W_ - 1] : 0.f;
        float a01 = (ym)       ? b[-W_]     : 0.f;
        float a02 = (ym && xp) ? b[-W_ + 1] : 0.f;
        float a10 = (xm)       ? b[-1]      : 0.f;
        float a12 = (xp)       ? b[1]       : 0.f;
        float a20 = (yp && xm) ? b[W_ - 1]  : 0.f;
        float a21 = (yp)       ? b[W_]      : 0.f;
        float a22 = (yp && xp) ? b[W_ + 1]  : 0.f;

        // sobel_h = [[1,0,-1],[2,0,-2],[1,0,-1]], ascending row-major FMA
        float gx = a00;                    // fma(1,a00,0)
        gx = fmaf(-1.f, a02, gx);
        gx = fmaf( 2.f, a10, gx);
        gx = fmaf(-2.f, a12, gx);
        gx = fmaf( 1.f, a20, gx);
        gx = fmaf(-1.f, a22, gx);
        // sobel_v = [[1,2,1],[0,0,0],[-1,-2,-1]], ascending row-major FMA
        float gy = a00;
        gy = fmaf( 2.f, a01, gy);
        gy = fmaf( 1.f, a02, gy);
        gy = fmaf(-1.f, a20, gy);
        gy = fmaf(-2.f, a21, gy);
        gy = fmaf(-1.f, a22, gy);

        mag = __fadd_rn(mag, sqrtf(fmaf(gx, gx, __fmul_rn(gy, gy))));
        sx  = __fadd_rn(sx, gx);
        sy  = __fadd_rn(sy, gy);
    }
    // first iteration adds to 0.f: rn(0+v) = v exactly, so sums are ((r+g)+b)

    // Exact emulation of:
    //   o = atan2(sy,sx) * (180/3.14159);  o = round((o+180)/45) * 45
    const float C = (float)(180.0 / 3.14159);   // NOTE: 3.14159, not pi
    float o  = atan2f(sy, sx);                   // libdevice __nv_atan2f (same as XLA)
    float ov = __fmul_rn(o, C);
    float t  = __fdiv_rn(__fadd_rn(ov, 180.0f), 45.0f);
    float q  = rintf(t);                         // half-even, matches jnp.round

    grad[idx]   = mag;
    orient[idx] = __fmul_rn(q, 45.0f);
    float thr = thr_p[0];
    early[idx]  = (mag < thr) ? 0.f : mag;
}

// ---------------------------------------------------------------------------
// Kernel 4: NMS + threshold.
// dir k offsets (dy,dx) from _dir_filters():
//   k: 0:(0,1) 1:(1,1) 2:(1,0) 3:(1,-1) 4:(0,-1) 5:(-1,-1) 6:(-1,0) 7:(-1,1)
// all_f[k](y,x) = rn(grad(y,x) - grad(y+dy,x+dx))  [zero pad], single rounding
// which matches the conv accumulation exactly.
// ---------------------------------------------------------------------------
__global__ void nms_k(const float* __restrict__ grad,
                      const float* __restrict__ orient,
                      const float* __restrict__ thr_p,
                      float* __restrict__ thin,
                      float* __restrict__ thresh) {
    int idx = blockIdx.x * blockDim.x + threadIdx.x;
    if (idx >= HW_) return;
    int x = idx & (W_ - 1);
    int y = idx >> LOG2W;

    const int dy[8] = { 0, 1, 1,  1,  0, -1, -1, -1 };
    const int dx[8] = { 1, 1, 0, -1, -1, -1,  0,  1 };

    float gm = grad[idx];
    int q  = (int)(orient[idx] * (1.0f / 45.0f));  // orient = 45*q exactly
    int kp = q & 7;
    int kn = (q + 4) & 7;

    int ypn = y + dy[kp], xpn = x + dx[kp];
    int ynn = y + dy[kn], xnn = x + dx[kn];
    float npix = (ypn >= 0 && ypn < H_ && xpn >= 0 && xpn < W_) ? grad[ypn * W_ + xpn] : 0.f;
    float nneg = (ynn >= 0 && ynn < H_ && xnn >= 0 && xnn < W_) ? grad[ynn * W_ + xnn] : 0.f;

    float pos = __fadd_rn(gm, -npix);
    float neg = __fadd_rn(gm, -nneg);
    float t = (fminf(pos, neg) > 0.f) ? gm : 0.f;

    thin[idx] = t;
    float thr = thr_p[0];
    thresh[idx] = (t < thr) ? 0.f : t;
}

// ---------------------------------------------------------------------------
// Launch
// Inputs: img[3HW], threshold[1], gauss_h[5], gauss_v[5], sobel_h[9],
//         sobel_v[9], dir_w[72]
// Output: [0,3HW) blurred | [3HW,4HW) grad | [4HW,5HW) orient |
//         [5HW,6HW) thin | [6HW,7HW) thresholded | [7HW,8HW) early
// ---------------------------------------------------------------------------
extern "C" void kernel_launch(void* const* d_in, const int* in_sizes, int n_in,
                              void* d_out, int out_size) {
    const float* img   = (const float*)d_in[0];
    const float* thr   = (const float*)d_in[1];
    const float* gauss = (const float*)d_in[2];

    float* out      = (float*)d_out;
    float* blurred  = out;
    float* grad     = out + 3 * HW_;
    float* orient   = out + 4 * HW_;
    float* thin     = out + 5 * HW_;
    float* thresh   = out + 6 * HW_;
    float* early    = out + 7 * HW_;

    const int T = 256;
    int blocks3 = (3 * HW_ + T - 1) / T;
    int blocks1 = (HW_ + T - 1) / T;

    blur_h_k<<<blocks3, T>>>(img, gauss);
    blur_v_k<<<blocks3, T>>>(gauss, blurred);
    sobel_k<<<blocks1, T>>>(blurred, thr, grad, orient, early);
    nms_k<<<blocks1, T>>>(grad, orient, thr, thin, thresh);
}

// round 4
// speedup vs baseline: 1.9774x; 1.9774x over previous
#include <cuda_runtime.h>
#include <math.h>

// Problem constants (fixed by reference: H = W = 2048)
#define H_ 2048
#define W_ 2048
#define HW_ (H_ * W_)
#define LOG2W 11

// ---------------------------------------------------------------------------
// Kernel 1: fused separable gaussian (1x5 then 5x1, zero pad 2).
// Tile 128x8 outputs per block (one channel), h-pass staged in smem.
// Arithmetic chains identical to the 2-kernel version (bit-exact).
// ---------------------------------------------------------------------------
#define TILE_X 128
#define TILE_Y 8
#define SROWS (TILE_Y + 4)

__global__ void blur_f_k(const float* __restrict__ img, const float* __restrict__ g,
                         float* __restrict__ blurred) {
    __shared__ float sh[SROWS][TILE_X];
    const int c = blockIdx.z;
    const int tileX0 = blockIdx.x * TILE_X;
    const int tileY0 = blockIdx.y * TILE_Y;
    const int t = threadIdx.x;          // 0..255
    const float* im = img + c * HW_;
    const float g0 = g[0], g1 = g[1], g2 = g[2], g3 = g[3], g4 = g[4];

    // ---- horizontal pass: SROWS x 32 float4-units = 384 units, 256 threads ----
    for (int u = t; u < SROWS * (TILE_X / 4); u += 256) {
        int r  = u >> 5;                 // 0..11
        int cx = (u & 31) * 4;
        int gy = tileY0 - 2 + r;
        float o0 = 0.f, o1 = 0.f, o2 = 0.f, o3 = 0.f;
        if (gy >= 0 && gy < H_) {
            const float* row = im + gy * W_;
            int gx = tileX0 + cx;
            float v[8];
#pragma unroll
            for (int j = 0; j < 8; ++j) {
                int xx = gx - 2 + j;
                v[j] = (xx >= 0 && xx < W_) ? __ldg(row + xx) : 0.f;
            }
            // acc = mul(g0,x0); fma(g1..g4) ascending — same chain as before
            o0 = fmaf(g4, v[4], fmaf(g3, v[3], fmaf(g2, v[2], fmaf(g1, v[1], __fmul_rn(g0, v[0])))));
            o1 = fmaf(g4, v[5], fmaf(g3, v[4], fmaf(g2, v[3], fmaf(g1, v[2], __fmul_rn(g0, v[1])))));
            o2 = fmaf(g4, v[6], fmaf(g3, v[5], fmaf(g2, v[4], fmaf(g1, v[3], __fmul_rn(g0, v[2])))));
            o3 = fmaf(g4, v[7], fmaf(g3, v[6], fmaf(g2, v[5], fmaf(g1, v[4], __fmul_rn(g0, v[3])))));
        }
        sh[r][cx]     = o0;
        sh[r][cx + 1] = o1;
        sh[r][cx + 2] = o2;
        sh[r][cx + 3] = o3;
    }
    __syncthreads();

    // ---- vertical pass: thread (tx,ty) -> float4 output ----
    int tx = t & 31, ty = t >> 5;
    int gy = tileY0 + ty;
    int gx = tileX0 + tx * 4;
    int cx = tx * 4;
    float4 o;
    {
        float acc;
        acc = __fmul_rn(g0, sh[ty][cx]);
        acc = fmaf(g1, sh[ty + 1][cx], acc);
        acc = fmaf(g2, sh[ty + 2][cx], acc);
        acc = fmaf(g3, sh[ty + 3][cx], acc);
        o.x = fmaf(g4, sh[ty + 4][cx], acc);
        acc = __fmul_rn(g0, sh[ty][cx + 1]);
        acc = fmaf(g1, sh[ty + 1][cx + 1], acc);
        acc = fmaf(g2, sh[ty + 2][cx + 1], acc);
        acc = fmaf(g3, sh[ty + 3][cx + 1], acc);
        o.y = fmaf(g4, sh[ty + 4][cx + 1], acc);
        acc = __fmul_rn(g0, sh[ty][cx + 2]);
        acc = fmaf(g1, sh[ty + 1][cx + 2], acc);
        acc = fmaf(g2, sh[ty + 2][cx + 2], acc);
        acc = fmaf(g3, sh[ty + 3][cx + 2], acc);
        o.z = fmaf(g4, sh[ty + 4][cx + 2], acc);
        acc = __fmul_rn(g0, sh[ty][cx + 3]);
        acc = fmaf(g1, sh[ty + 1][cx + 3], acc);
        acc = fmaf(g2, sh[ty + 2][cx + 3], acc);
        acc = fmaf(g3, sh[ty + 3][cx + 3], acc);
        o.w = fmaf(g4, sh[ty + 4][cx + 3], acc);
    }
    *(float4*)(blurred + c * HW_ + gy * W_ + gx) = o;
}

// ---------------------------------------------------------------------------
// Kernel 2: Sobel (zero pad 1) + grad_mag + orient + early_threshold.
// 4 px/thread, float4 I/O. FMA chains identical to R3 (bit-exact).
// ---------------------------------------------------------------------------
__global__ void sobel_k(const float* __restrict__ blurred,
                        const float* __restrict__ thr_p,
                        float* __restrict__ grad,
                        float* __restrict__ orient,
                        float* __restrict__ early) {
    int t4 = blockIdx.x * blockDim.x + threadIdx.x;   // float4 index
    int idx = t4 * 4;
    int x = idx & (W_ - 1);
    int y = idx >> LOG2W;
    bool ym = (y > 0), yp = (y < H_ - 1);
    bool xl = (x > 0), xr = (x + 4 < W_);

    float mag[4] = {0.f, 0.f, 0.f, 0.f};
    float sx[4]  = {0.f, 0.f, 0.f, 0.f};
    float sy[4]  = {0.f, 0.f, 0.f, 0.f};

#pragma unroll
    for (int c = 0; c < 3; ++c) {
        const float* b = blurred + c * HW_ + y * W_ + x;
        float tp[6], md[6], bt[6];
        // top row (y-1)
        if (ym) {
            float4 v = __ldg((const float4*)(b - W_));
            tp[1] = v.x; tp[2] = v.y; tp[3] = v.z; tp[4] = v.w;
            tp[0] = xl ? __ldg(b - W_ - 1) : 0.f;
            tp[5] = xr ? __ldg(b - W_ + 4) : 0.f;
        } else {
            tp[0] = tp[1] = tp[2] = tp[3] = tp[4] = tp[5] = 0.f;
        }
        // mid row (y) — center column unused by sobel, only +-1 cols needed
        {
            float4 v = __ldg((const float4*)b);
            md[1] = v.x; md[2] = v.y; md[3] = v.z; md[4] = v.w;
            md[0] = xl ? __ldg(b - 1) : 0.f;
            md[5] = xr ? __ldg(b + 4) : 0.f;
        }
        // bottom row (y+1)
        if (yp) {
            float4 v = __ldg((const float4*)(b + W_));
            bt[1] = v.x; bt[2] = v.y; bt[3] = v.z; bt[4] = v.w;
            bt[0] = xl ? __ldg(b + W_ - 1) : 0.f;
            bt[5] = xr ? __ldg(b + W_ + 4) : 0.f;
        } else {
            bt[0] = bt[1] = bt[2] = bt[3] = bt[4] = bt[5] = 0.f;
        }
#pragma unroll
        for (int i = 0; i < 4; ++i) {
            float a00 = tp[i], a01 = tp[i + 1], a02 = tp[i + 2];
            float a10 = md[i],                  a12 = md[i + 2];
            float a20 = bt[i], a21 = bt[i + 1], a22 = bt[i + 2];
            // sobel_h = [[1,0,-1],[2,0,-2],[1,0,-1]], ascending row-major FMA
            float gx = a00;
            gx = fmaf(-1.f, a02, gx);
            gx = fmaf( 2.f, a10, gx);
            gx = fmaf(-2.f, a12, gx);
            gx = fmaf( 1.f, a20, gx);
            gx = fmaf(-1.f, a22, gx);
            // sobel_v = transpose
            float gy = a00;
            gy = fmaf( 2.f, a01, gy);
            gy = fmaf( 1.f, a02, gy);
            gy = fmaf(-1.f, a20, gy);
            gy = fmaf(-2.f, a21, gy);
            gy = fmaf(-1.f, a22, gy);

            mag[i] = __fadd_rn(mag[i], sqrtf(fmaf(gx, gx, __fmul_rn(gy, gy))));
            sx[i]  = __fadd_rn(sx[i], gx);
            sy[i]  = __fadd_rn(sy[i], gy);
        }
    }

    const float C = (float)(180.0 / 3.14159);   // NOTE: 3.14159, not pi
    float thr = __ldg(thr_p);
    float4 gm4, or4, ea4;
    float* gmA = (float*)&gm4;
    float* orA = (float*)&or4;
    float* eaA = (float*)&ea4;
#pragma unroll
    for (int i = 0; i < 4; ++i) {
        float o  = atan2f(sy[i], sx[i]);         // libdevice __nv_atan2f (same as XLA)
        float ov = __fmul_rn(o, C);
        float tt = __fdiv_rn(__fadd_rn(ov, 180.0f), 45.0f);
        float q  = rintf(tt);                    // half-even (jnp.round)
        gmA[i] = mag[i];
        orA[i] = __fmul_rn(q, 45.0f);
        eaA[i] = (mag[i] < thr) ? 0.f : mag[i];
    }
    *(float4*)(grad + idx)   = gm4;
    *(float4*)(orient + idx) = or4;
    *(float4*)(early + idx)  = ea4;
}

// ---------------------------------------------------------------------------
// Kernel 3: NMS + threshold, 4 px/thread.
// dir k offsets (dy,dx): 0:(0,1) 1:(1,1) 2:(1,0) 3:(1,-1) 4:(0,-1)
//                        5:(-1,-1) 6:(-1,0) 7:(-1,1)
// Packed nibble LUTs (value+1 per direction) avoid local-memory arrays.
// ---------------------------------------------------------------------------
__global__ void nms_k(const float* __restrict__ grad,
                      const float* __restrict__ orient,
                      const float* __restrict__ thr_p,
                      float* __restrict__ thin,
                      float* __restrict__ thresh) {
    int t4 = blockIdx.x * blockDim.x + threadIdx.x;
    int idx = t4 * 4;
    int x = idx & (W_ - 1);
    int y = idx >> LOG2W;

    const unsigned DYP = 0x00012221u;   // nibble k = dy[k]+1
    const unsigned DXP = 0x21000122u;   // nibble k = dx[k]+1

    float4 gm4 = __ldg((const float4*)(grad + idx));
    float4 or4 = __ldg((const float4*)(orient + idx));
    float thr = __ldg(thr_p);
    const float* gmA = (const float*)&gm4;
    const float* orA = (const float*)&or4;

    float4 th4, ts4;
    float* thA = (float*)&th4;
    float* tsA = (float*)&ts4;
#pragma unroll
    for (int i = 0; i < 4; ++i) {
        float gm = gmA[i];
        int q  = (int)(orA[i] * (1.0f / 45.0f));   // orient = 45*q exactly
        int kp = q & 7;
        int kn = (q + 4) & 7;

        int dyp = (int)((DYP >> (kp * 4)) & 3u) - 1;
        int dxp = (int)((DXP >> (kp * 4)) & 3u) - 1;
        int dyn = (int)((DYP >> (kn * 4)) & 3u) - 1;
        int dxn = (int)((DXP >> (kn * 4)) & 3u) - 1;

        int yp2 = y + dyp, xp2 = x + i + dxp;
        int yn2 = y + dyn, xn2 = x + i + dxn;
        float np = ((unsigned)yp2 < H_ && (unsigned)xp2 < W_)
                   ? __ldg(grad + yp2 * W_ + xp2) : 0.f;
        float nn = ((unsigned)yn2 < H_ && (unsigned)xn2 < W_)
                   ? __ldg(grad + yn2 * W_ + xn2) : 0.f;

        float pos = __fadd_rn(gm, -np);
        float neg = __fadd_rn(gm, -nn);
        float tv = (fminf(pos, neg) > 0.f) ? gm : 0.f;
        thA[i] = tv;
        tsA[i] = (tv < thr) ? 0.f : tv;
    }
    *(float4*)(thin + idx)   = th4;
    *(float4*)(thresh + idx) = ts4;
}

// ---------------------------------------------------------------------------
// Launch
// Inputs: img[3HW], threshold[1], gauss_h[5], gauss_v[5], sobel_h[9],
//         sobel_v[9], dir_w[72]
// Output: [0,3HW) blurred | [3HW,4HW) grad | [4HW,5HW) orient |
//         [5HW,6HW) thin | [6HW,7HW) thresholded | [7HW,8HW) early
// ---------------------------------------------------------------------------
extern "C" void kernel_launch(void* const* d_in, const int* in_sizes, int n_in,
                              void* d_out, int out_size) {
    const float* img   = (const float*)d_in[0];
    const float* thr   = (const float*)d_in[1];
    const float* gauss = (const float*)d_in[2];

    float* out      = (float*)d_out;
    float* blurred  = out;
    float* grad     = out + 3 * HW_;
    float* orient   = out + 4 * HW_;
    float* thin     = out + 5 * HW_;
    float* thresh   = out + 6 * HW_;
    float* early    = out + 7 * HW_;

    dim3 bgrid(W_ / TILE_X, H_ / TILE_Y, 3);   // 16 x 256 x 3
    blur_f_k<<<bgrid, 256>>>(img, gauss, blurred);

    int blocks1 = (HW_ / 4 + 255) / 256;        // 4096
    sobel_k<<<blocks1, 256>>>(blurred, thr, grad, orient, early);
    nms_k<<<blocks1, 256>>>(grad, orient, thr, thin, thresh);
}

// round 5
// speedup vs baseline: 2.2671x; 1.1465x over previous
#include <cuda_runtime.h>
#include <math.h>

// Problem constants (fixed by reference: H = W = 2048)
#define H_ 2048
#define W_ 2048
#define HW_ (H_ * W_)
#define LOG2W 11

// ---------------------------------------------------------------------------
// Kernel 1: fused separable gaussian (1x5 then 5x1, zero pad 2).
// Tile 128x16 outputs per block (one channel). Fully vectorized:
// h-pass = 3x LDG.128 + 1x STS.128 per float4 unit; v-pass = 5x LDS.128 +
// 1x STG.128. Arithmetic chains identical to prior rounds (bit-exact).
// ---------------------------------------------------------------------------
#define TILE_X 128
#define TILE_Y 16
#define SROWS (TILE_Y + 4)
#define TX4 (TILE_X / 4)

__global__ void blur_f_k(const float* __restrict__ img, const float* __restrict__ g,
                         float* __restrict__ blurred) {
    __shared__ float4 sh4[SROWS][TX4];
    const int c = blockIdx.z;
    const int tileX0 = blockIdx.x * TILE_X;
    const int tileY0 = blockIdx.y * TILE_Y;
    const int t = threadIdx.x;          // 0..255
    const float* im = img + c * HW_;
    const float g0 = g[0], g1 = g[1], g2 = g[2], g3 = g[3], g4 = g[4];
    const float4 z4 = make_float4(0.f, 0.f, 0.f, 0.f);

    // ---- horizontal pass: SROWS x TX4 = 640 float4-units, 256 threads ----
    for (int u = t; u < SROWS * TX4; u += 256) {
        int r   = u >> 5;               // 0..SROWS-1  (TX4 == 32)
        int cx4 = u & 31;
        int gy  = tileY0 - 2 + r;
        float4 o = z4;
        if (gy >= 0 && gy < H_) {
            const float4* row4 = (const float4*)(im + gy * W_);
            int gx = tileX0 + cx4 * 4;
            // gx is a multiple of 4: (gx-2 >= 0) <=> (gx-4 >= 0),
            //                        (gx+5 < W) <=> (gx+4 < W)
            float4 L = (gx >= 4)       ? __ldg(row4 + (gx >> 2) - 1) : z4;
            float4 M =                   __ldg(row4 + (gx >> 2));
            float4 R = (gx + 4 < W_)   ? __ldg(row4 + (gx >> 2) + 1) : z4;
            float v0 = L.z, v1 = L.w;
            float v2 = M.x, v3 = M.y, v4 = M.z, v5 = M.w;
            float v6 = R.x, v7 = R.y;
            // acc = mul(g0,x0); fma(g1..g4) ascending — same chain as before
            o.x = fmaf(g4, v4, fmaf(g3, v3, fmaf(g2, v2, fmaf(g1, v1, __fmul_rn(g0, v0)))));
            o.y = fmaf(g4, v5, fmaf(g3, v4, fmaf(g2, v3, fmaf(g1, v2, __fmul_rn(g0, v1)))));
            o.z = fmaf(g4, v6, fmaf(g3, v5, fmaf(g2, v4, fmaf(g1, v3, __fmul_rn(g0, v2)))));
            o.w = fmaf(g4, v7, fmaf(g3, v6, fmaf(g2, v5, fmaf(g1, v4, __fmul_rn(g0, v3)))));
        }
        sh4[r][cx4] = o;
    }
    __syncthreads();

    // ---- vertical pass: TILE_Y x TX4 = 512 float4 outputs, 2 per thread ----
    for (int w = t; w < TILE_Y * TX4; w += 256) {
        int ty  = w >> 5;
        int tx4 = w & 31;
        float4 r0 = sh4[ty][tx4];
        float4 r1 = sh4[ty + 1][tx4];
        float4 r2 = sh4[ty + 2][tx4];
        float4 r3 = sh4[ty + 3][tx4];
        float4 r4 = sh4[ty + 4][tx4];
        float4 o;
        o.x = fmaf(g4, r4.x, fmaf(g3, r3.x, fmaf(g2, r2.x, fmaf(g1, r1.x, __fmul_rn(g0, r0.x)))));
        o.y = fmaf(g4, r4.y, fmaf(g3, r3.y, fmaf(g2, r2.y, fmaf(g1, r1.y, __fmul_rn(g0, r0.y)))));
        o.z = fmaf(g4, r4.z, fmaf(g3, r3.z, fmaf(g2, r2.z, fmaf(g1, r1.z, __fmul_rn(g0, r0.z)))));
        o.w = fmaf(g4, r4.w, fmaf(g3, r3.w, fmaf(g2, r2.w, fmaf(g1, r1.w, __fmul_rn(g0, r0.w)))));
        int gy = tileY0 + ty;
        int gx = tileX0 + tx4 * 4;
        *(float4*)(blurred + c * HW_ + gy * W_ + gx) = o;
    }
}

// ---------------------------------------------------------------------------
// Kernel 2: Sobel (zero pad 1) + grad_mag + orient + early_threshold.
// 4 px/thread, float4 I/O. FMA chains identical to R3 (bit-exact).
// ---------------------------------------------------------------------------
__global__ void sobel_k(const float* __restrict__ blurred,
                        const float* __restrict__ thr_p,
                        float* __restrict__ grad,
                        float* __restrict__ orient,
                        float* __restrict__ early) {
    int t4 = blockIdx.x * blockDim.x + threadIdx.x;   // float4 index
    int idx = t4 * 4;
    int x = idx & (W_ - 1);
    int y = idx >> LOG2W;
    bool ym = (y > 0), yp = (y < H_ - 1);
    bool xl = (x > 0), xr = (x + 4 < W_);

    float mag[4] = {0.f, 0.f, 0.f, 0.f};
    float sx[4]  = {0.f, 0.f, 0.f, 0.f};
    float sy[4]  = {0.f, 0.f, 0.f, 0.f};

#pragma unroll
    for (int c = 0; c < 3; ++c) {
        const float* b = blurred + c * HW_ + y * W_ + x;
        float tp[6], md[6], bt[6];
        if (ym) {
            float4 v = __ldg((const float4*)(b - W_));
            tp[1] = v.x; tp[2] = v.y; tp[3] = v.z; tp[4] = v.w;
            tp[0] = xl ? __ldg(b - W_ - 1) : 0.f;
            tp[5] = xr ? __ldg(b - W_ + 4) : 0.f;
        } else {
            tp[0] = tp[1] = tp[2] = tp[3] = tp[4] = tp[5] = 0.f;
        }
        {
            float4 v = __ldg((const float4*)b);
            md[1] = v.x; md[2] = v.y; md[3] = v.z; md[4] = v.w;
            md[0] = xl ? __ldg(b - 1) : 0.f;
            md[5] = xr ? __ldg(b + 4) : 0.f;
        }
        if (yp) {
            float4 v = __ldg((const float4*)(b + W_));
            bt[1] = v.x; bt[2] = v.y; bt[3] = v.z; bt[4] = v.w;
            bt[0] = xl ? __ldg(b + W_ - 1) : 0.f;
            bt[5] = xr ? __ldg(b + W_ + 4) : 0.f;
        } else {
            bt[0] = bt[1] = bt[2] = bt[3] = bt[4] = bt[5] = 0.f;
        }
#pragma unroll
        for (int i = 0; i < 4; ++i) {
            float a00 = tp[i], a01 = tp[i + 1], a02 = tp[i + 2];
            float a10 = md[i],                  a12 = md[i + 2];
            float a20 = bt[i], a21 = bt[i + 1], a22 = bt[i + 2];
            float gx = a00;
            gx = fmaf(-1.f, a02, gx);
            gx = fmaf( 2.f, a10, gx);
            gx = fmaf(-2.f, a12, gx);
            gx = fmaf( 1.f, a20, gx);
            gx = fmaf(-1.f, a22, gx);
            float gy = a00;
            gy = fmaf( 2.f, a01, gy);
            gy = fmaf( 1.f, a02, gy);
            gy = fmaf(-1.f, a20, gy);
            gy = fmaf(-2.f, a21, gy);
            gy = fmaf(-1.f, a22, gy);

            mag[i] = __fadd_rn(mag[i], sqrtf(fmaf(gx, gx, __fmul_rn(gy, gy))));
            sx[i]  = __fadd_rn(sx[i], gx);
            sy[i]  = __fadd_rn(sy[i], gy);
        }
    }

    const float C = (float)(180.0 / 3.14159);   // NOTE: 3.14159, not pi
    float thr = __ldg(thr_p);
    float4 gm4, or4, ea4;
    float* gmA = (float*)&gm4;
    float* orA = (float*)&or4;
    float* eaA = (float*)&ea4;
#pragma unroll
    for (int i = 0; i < 4; ++i) {
        float o  = atan2f(sy[i], sx[i]);         // libdevice __nv_atan2f (same as XLA)
        float ov = __fmul_rn(o, C);
        float tt = __fdiv_rn(__fadd_rn(ov, 180.0f), 45.0f);
        float q  = rintf(tt);                    // half-even (jnp.round)
        gmA[i] = mag[i];
        orA[i] = __fmul_rn(q, 45.0f);
        eaA[i] = (mag[i] < thr) ? 0.f : mag[i];
    }
    *(float4*)(grad + idx)   = gm4;
    *(float4*)(orient + idx) = or4;
    *(float4*)(early + idx)  = ea4;
}

// ---------------------------------------------------------------------------
// Kernel 3: NMS + threshold, 4 px/thread, nibble-packed direction LUTs.
// ---------------------------------------------------------------------------
__global__ void nms_k(const float* __restrict__ grad,
                      const float* __restrict__ orient,
                      const float* __restrict__ thr_p,
                      float* __restrict__ thin,
                      float* __restrict__ thresh) {
    int t4 = blockIdx.x * blockDim.x + threadIdx.x;
    int idx = t4 * 4;
    int x = idx & (W_ - 1);
    int y = idx >> LOG2W;

    const unsigned DYP = 0x00012221u;   // nibble k = dy[k]+1
    const unsigned DXP = 0x21000122u;   // nibble k = dx[k]+1

    float4 gm4 = __ldg((const float4*)(grad + idx));
    float4 or4 = __ldg((const float4*)(orient + idx));
    float thr = __ldg(thr_p);
    const float* gmA = (const float*)&gm4;
    const float* orA = (const float*)&or4;

    float4 th4, ts4;
    float* thA = (float*)&th4;
    float* tsA = (float*)&ts4;
#pragma unroll
    for (int i = 0; i < 4; ++i) {
        float gm = gmA[i];
        int q  = (int)(orA[i] * (1.0f / 45.0f));   // orient = 45*q exactly
        int kp = q & 7;
        int kn = (q + 4) & 7;

        int dyp = (int)((DYP >> (kp * 4)) & 3u) - 1;
        int dxp = (int)((DXP >> (kp * 4)) & 3u) - 1;
        int dyn = (int)((DYP >> (kn * 4)) & 3u) - 1;
        int dxn = (int)((DXP >> (kn * 4)) & 3u) - 1;

        int yp2 = y + dyp, xp2 = x + i + dxp;
        int yn2 = y + dyn, xn2 = x + i + dxn;
        float np = ((unsigned)yp2 < H_ && (unsigned)xp2 < W_)
                   ? __ldg(grad + yp2 * W_ + xp2) : 0.f;
        float nn = ((unsigned)yn2 < H_ && (unsigned)xn2 < W_)
                   ? __ldg(grad + yn2 * W_ + xn2) : 0.f;

        float pos = __fadd_rn(gm, -np);
        float neg = __fadd_rn(gm, -nn);
        float tv = (fminf(pos, neg) > 0.f) ? gm : 0.f;
        thA[i] = tv;
        tsA[i] = (tv < thr) ? 0.f : tv;
    }
    *(float4*)(thin + idx)   = th4;
    *(float4*)(thresh + idx) = ts4;
}

// ---------------------------------------------------------------------------
// Launch
// Inputs: img[3HW], threshold[1], gauss_h[5], gauss_v[5], sobel_h[9],
//         sobel_v[9], dir_w[72]
// Output: [0,3HW) blurred | [3HW,4HW) grad | [4HW,5HW) orient |
//         [5HW,6HW) thin | [6HW,7HW) thresholded | [7HW,8HW) early
// ---------------------------------------------------------------------------
extern "C" void kernel_launch(void* const* d_in, const int* in_sizes, int n_in,
                              void* d_out, int out_size) {
    const float* img   = (const float*)d_in[0];
    const float* thr   = (const float*)d_in[1];
    const float* gauss = (const float*)d_in[2];

    float* out      = (float*)d_out;
    float* blurred  = out;
    float* grad     = out + 3 * HW_;
    float* orient   = out + 4 * HW_;
    float* thin     = out + 5 * HW_;
    float* thresh   = out + 6 * HW_;
    float* early    = out + 7 * HW_;

    dim3 bgrid(W_ / TILE_X, H_ / TILE_Y, 3);   // 16 x 128 x 3
    blur_f_k<<<bgrid, 256>>>(img, gauss, blurred);

    int blocks1 = (HW_ / 4 + 255) / 256;        // 4096
    sobel_k<<<blocks1, 256>>>(blurred, thr, grad, orient, early);
    nms_k<<<blocks1, 256>>>(grad, orient, thr, thin, thresh);
}

// round 6
// speedup vs baseline: 2.3514x; 1.0372x over previous
#include <cuda_runtime.h>
#include <math.h>

// Problem constants (fixed by reference: H = W = 2048)
#define H_ 2048
#define W_ 2048
#define HW_ (H_ * W_)
#define LOG2W 11

// ---------------------------------------------------------------------------
// Kernel 1: fused separable gaussian (1x5 then 5x1, zero pad 2).
// Tile 128x32 per block/channel. h-pass: 3x LDG.128 + 1x STS.128 per unit.
// v-pass: register rolling window — 8x LDS.128 -> 4 outputs per thread.
// Arithmetic chains identical to prior rounds (bit-exact).
// ---------------------------------------------------------------------------
#define TILE_X 128
#define TILE_Y 32
#define SROWS (TILE_Y + 4)
#define TX4 (TILE_X / 4)

__global__ void blur_f_k(const float* __restrict__ img, const float* __restrict__ g,
                         float* __restrict__ blurred) {
    __shared__ float4 sh4[SROWS][TX4];
    const int c = blockIdx.z;
    const int tileX0 = blockIdx.x * TILE_X;
    const int tileY0 = blockIdx.y * TILE_Y;
    const int t = threadIdx.x;          // 0..255
    const float* im = img + c * HW_;
    const float g0 = g[0], g1 = g[1], g2 = g[2], g3 = g[3], g4 = g[4];
    const float4 z4 = make_float4(0.f, 0.f, 0.f, 0.f);

    // ---- horizontal pass: SROWS x TX4 = 1152 float4-units, 256 threads ----
    for (int u = t; u < SROWS * TX4; u += 256) {
        int r   = u >> 5;               // 0..SROWS-1  (TX4 == 32)
        int cx4 = u & 31;
        int gy  = tileY0 - 2 + r;
        float4 o = z4;
        if (gy >= 0 && gy < H_) {
            const float4* row4 = (const float4*)(im + gy * W_);
            int gx = tileX0 + cx4 * 4;
            // gx multiple of 4: (gx-2>=0) <=> (gx-4>=0); (gx+5<W) <=> (gx+4<W)
            float4 L = (gx >= 4)     ? __ldg(row4 + (gx >> 2) - 1) : z4;
            float4 M =                 __ldg(row4 + (gx >> 2));
            float4 R = (gx + 4 < W_) ? __ldg(row4 + (gx >> 2) + 1) : z4;
            float v0 = L.z, v1 = L.w;
            float v2 = M.x, v3 = M.y, v4 = M.z, v5 = M.w;
            float v6 = R.x, v7 = R.y;
            o.x = fmaf(g4, v4, fmaf(g3, v3, fmaf(g2, v2, fmaf(g1, v1, __fmul_rn(g0, v0)))));
            o.y = fmaf(g4, v5, fmaf(g3, v4, fmaf(g2, v3, fmaf(g1, v2, __fmul_rn(g0, v1)))));
            o.z = fmaf(g4, v6, fmaf(g3, v5, fmaf(g2, v4, fmaf(g1, v3, __fmul_rn(g0, v2)))));
            o.w = fmaf(g4, v7, fmaf(g3, v6, fmaf(g2, v5, fmaf(g1, v4, __fmul_rn(g0, v3)))));
        }
        sh4[r][cx4] = o;
    }
    __syncthreads();

    // ---- vertical pass: thread owns a 4-row column segment (rolling regs) ----
    {
        int ty0 = (t >> 5) * 4;        // 0,4,...,28
        int tx4 = t & 31;
        float4 r0 = sh4[ty0    ][tx4];
        float4 r1 = sh4[ty0 + 1][tx4];
        float4 r2 = sh4[ty0 + 2][tx4];
        float4 r3 = sh4[ty0 + 3][tx4];
        float4 r4 = sh4[ty0 + 4][tx4];
        float4 r5 = sh4[ty0 + 5][tx4];
        float4 r6 = sh4[ty0 + 6][tx4];
        float4 r7 = sh4[ty0 + 7][tx4];
        float* base = blurred + c * HW_ + (tileY0 + ty0) * W_ + tileX0 + tx4 * 4;

#define VBLUR(d, a0, a1, a2, a3, a4)                                                               \
        {                                                                                           \
            float4 o;                                                                               \
            o.x = fmaf(g4, a4.x, fmaf(g3, a3.x, fmaf(g2, a2.x, fmaf(g1, a1.x, __fmul_rn(g0, a0.x))))); \
            o.y = fmaf(g4, a4.y, fmaf(g3, a3.y, fmaf(g2, a2.y, fmaf(g1, a1.y, __fmul_rn(g0, a0.y))))); \
            o.z = fmaf(g4, a4.z, fmaf(g3, a3.z, fmaf(g2, a2.z, fmaf(g1, a1.z, __fmul_rn(g0, a0.z))))); \
            o.w = fmaf(g4, a4.w, fmaf(g3, a3.w, fmaf(g2, a2.w, fmaf(g1, a1.w, __fmul_rn(g0, a0.w))))); \
            *(float4*)(base + (d) * W_) = o;                                                        \
        }
        VBLUR(0, r0, r1, r2, r3, r4)
        VBLUR(1, r1, r2, r3, r4, r5)
        VBLUR(2, r2, r3, r4, r5, r6)
        VBLUR(3, r3, r4, r5, r6, r7)
#undef VBLUR
    }
}

// ---------------------------------------------------------------------------
// Kernel 2: Sobel (zero pad 1) + grad_mag + orient + early_threshold.
// 4 px/thread, float4 I/O. FMA chains identical to R3 (bit-exact).
// ---------------------------------------------------------------------------
__global__ void sobel_k(const float* __restrict__ blurred,
                        const float* __restrict__ thr_p,
                        float* __restrict__ grad,
                        float* __restrict__ orient,
                        float* __restrict__ early) {
    int t4 = blockIdx.x * blockDim.x + threadIdx.x;   // float4 index
    int idx = t4 * 4;
    int x = idx & (W_ - 1);
    int y = idx >> LOG2W;
    bool ym = (y > 0), yp = (y < H_ - 1);
    bool xl = (x > 0), xr = (x + 4 < W_);

    float mag[4] = {0.f, 0.f, 0.f, 0.f};
    float sx[4]  = {0.f, 0.f, 0.f, 0.f};
    float sy[4]  = {0.f, 0.f, 0.f, 0.f};

#pragma unroll
    for (int c = 0; c < 3; ++c) {
        const float* b = blurred + c * HW_ + y * W_ + x;
        float tp[6], md[6], bt[6];
        if (ym) {
            float4 v = __ldg((const float4*)(b - W_));
            tp[1] = v.x; tp[2] = v.y; tp[3] = v.z; tp[4] = v.w;
            tp[0] = xl ? __ldg(b - W_ - 1) : 0.f;
            tp[5] = xr ? __ldg(b - W_ + 4) : 0.f;
        } else {
            tp[0] = tp[1] = tp[2] = tp[3] = tp[4] = tp[5] = 0.f;
        }
        {
            float4 v = __ldg((const float4*)b);
            md[1] = v.x; md[2] = v.y; md[3] = v.z; md[4] = v.w;
            md[0] = xl ? __ldg(b - 1) : 0.f;
            md[5] = xr ? __ldg(b + 4) : 0.f;
        }
        if (yp) {
            float4 v = __ldg((const float4*)(b + W_));
            bt[1] = v.x; bt[2] = v.y; bt[3] = v.z; bt[4] = v.w;
            bt[0] = xl ? __ldg(b + W_ - 1) : 0.f;
            bt[5] = xr ? __ldg(b + W_ + 4) : 0.f;
        } else {
            bt[0] = bt[1] = bt[2] = bt[3] = bt[4] = bt[5] = 0.f;
        }
#pragma unroll
        for (int i = 0; i < 4; ++i) {
            float a00 = tp[i], a01 = tp[i + 1], a02 = tp[i + 2];
            float a10 = md[i],                  a12 = md[i + 2];
            float a20 = bt[i], a21 = bt[i + 1], a22 = bt[i + 2];
            float gx = a00;
            gx = fmaf(-1.f, a02, gx);
            gx = fmaf( 2.f, a10, gx);
            gx = fmaf(-2.f, a12, gx);
            gx = fmaf( 1.f, a20, gx);
            gx = fmaf(-1.f, a22, gx);
            float gy = a00;
            gy = fmaf( 2.f, a01, gy);
            gy = fmaf( 1.f, a02, gy);
            gy = fmaf(-1.f, a20, gy);
            gy = fmaf(-2.f, a21, gy);
            gy = fmaf(-1.f, a22, gy);

            mag[i] = __fadd_rn(mag[i], sqrtf(fmaf(gx, gx, __fmul_rn(gy, gy))));
            sx[i]  = __fadd_rn(sx[i], gx);
            sy[i]  = __fadd_rn(sy[i], gy);
        }
    }

    const float C = (float)(180.0 / 3.14159);   // NOTE: 3.14159, not pi
    float thr = __ldg(thr_p);
    float4 gm4, or4, ea4;
    float* gmA = (float*)&gm4;
    float* orA = (float*)&or4;
    float* eaA = (float*)&ea4;
#pragma unroll
    for (int i = 0; i < 4; ++i) {
        float o  = atan2f(sy[i], sx[i]);         // libdevice __nv_atan2f (same as XLA)
        float ov = __fmul_rn(o, C);
        float tt = __fdiv_rn(__fadd_rn(ov, 180.0f), 45.0f);
        float q  = rintf(tt);                    // half-even (jnp.round)
        gmA[i] = mag[i];
        orA[i] = __fmul_rn(q, 45.0f);
        eaA[i] = (mag[i] < thr) ? 0.f : mag[i];
    }
    *(float4*)(grad + idx)   = gm4;
    *(float4*)(orient + idx) = or4;
    *(float4*)(early + idx)  = ea4;
}

// ---------------------------------------------------------------------------
// Kernel 3: NMS + threshold, 4 px/thread.
// Neighbors selected from a 3x6 register patch (coalesced loads, zero-filled
// at borders == bounds-checked loads) via nested SELs — no divergent LDGs.
// dir k offsets (dy,dx): 0:(0,1) 1:(1,1) 2:(1,0) 3:(1,-1) 4:(0,-1)
//                        5:(-1,-1) 6:(-1,0) 7:(-1,1)
// ---------------------------------------------------------------------------
__global__ void nms_k(const float* __restrict__ grad,
                      const float* __restrict__ orient,
                      const float* __restrict__ thr_p,
                      float* __restrict__ thin,
                      float* __restrict__ thresh) {
    int t4 = blockIdx.x * blockDim.x + threadIdx.x;
    int idx = t4 * 4;
    int x = idx & (W_ - 1);
    int y = idx >> LOG2W;
    bool ym = (y > 0), yp = (y < H_ - 1);
    bool xl = (x > 0), xr = (x + 4 < W_);

    const unsigned DYP = 0x00012221u;   // nibble k = dy[k]+1
    const unsigned DXP = 0x21000122u;   // nibble k = dx[k]+1

    const float* b = grad + y * W_ + x;
    float tp[6], md[6], bt[6];
    if (ym) {
        float4 v = __ldg((const float4*)(b - W_));
        tp[1] = v.x; tp[2] = v.y; tp[3] = v.z; tp[4] = v.w;
        tp[0] = xl ? __ldg(b - W_ - 1) : 0.f;
        tp[5] = xr ? __ldg(b - W_ + 4) : 0.f;
    } else {
        tp[0] = tp[1] = tp[2] = tp[3] = tp[4] = tp[5] = 0.f;
    }
    {
        float4 v = __ldg((const float4*)b);
        md[1] = v.x; md[2] = v.y; md[3] = v.z; md[4] = v.w;
        md[0] = xl ? __ldg(b - 1) : 0.f;
        md[5] = xr ? __ldg(b + 4) : 0.f;
    }
    if (yp) {
        float4 v = __ldg((const float4*)(b + W_));
        bt[1] = v.x; bt[2] = v.y; bt[3] = v.z; bt[4] = v.w;
        bt[0] = xl ? __ldg(b + W_ - 1) : 0.f;
        bt[5] = xr ? __ldg(b + W_ + 4) : 0.f;
    } else {
        bt[0] = bt[1] = bt[2] = bt[3] = bt[4] = bt[5] = 0.f;
    }

    float4 or4 = __ldg((const float4*)(orient + idx));
    float thr = __ldg(thr_p);
    const float* orA = (const float*)&or4;

    float4 th4, ts4;
    float* thA = (float*)&th4;
    float* tsA = (float*)&ts4;
#pragma unroll
    for (int i = 0; i < 4; ++i) {
        float gm = md[i + 1];
        int q  = (int)(orA[i] * (1.0f / 45.0f));   // orient = 45*q exactly
        int kp = q & 7;
        int kn = (q + 4) & 7;

        int dyp = (int)((DYP >> (kp * 4)) & 3u) - 1;
        int dxp = (int)((DXP >> (kp * 4)) & 3u) - 1;
        int dyn = (int)((DYP >> (kn * 4)) & 3u) - 1;
        int dxn = (int)((DXP >> (kn * 4)) & 3u) - 1;

        // neighbor = patch[1+dy][i+1+dx]; constant-index accesses + SELs
        float tT = (dxp < 0) ? tp[i] : ((dxp > 0) ? tp[i + 2] : tp[i + 1]);
        float tM = (dxp < 0) ? md[i] : ((dxp > 0) ? md[i + 2] : md[i + 1]);
        float tB = (dxp < 0) ? bt[i] : ((dxp > 0) ? bt[i + 2] : bt[i + 1]);
        float np = (dyp < 0) ? tT : ((dyp > 0) ? tB : tM);

        float uT = (dxn < 0) ? tp[i] : ((dxn > 0) ? tp[i + 2] : tp[i + 1]);
        float uM = (dxn < 0) ? md[i] : ((dxn > 0) ? md[i + 2] : md[i + 1]);
        float uB = (dxn < 0) ? bt[i] : ((dxn > 0) ? bt[i + 2] : bt[i + 1]);
        float nn = (dyn < 0) ? uT : ((dyn > 0) ? uB : uM);

        float pos = __fadd_rn(gm, -np);
        float neg = __fadd_rn(gm, -nn);
        float tv = (fminf(pos, neg) > 0.f) ? gm : 0.f;
        thA[i] = tv;
        tsA[i] = (tv < thr) ? 0.f : tv;
    }
    *(float4*)(thin + idx)   = th4;
    *(float4*)(thresh + idx) = ts4;
}

// ---------------------------------------------------------------------------
// Launch
// Inputs: img[3HW], threshold[1], gauss_h[5], gauss_v[5], sobel_h[9],
//         sobel_v[9], dir_w[72]
// Output: [0,3HW) blurred | [3HW,4HW) grad | [4HW,5HW) orient |
//         [5HW,6HW) thin | [6HW,7HW) thresholded | [7HW,8HW) early
// ---------------------------------------------------------------------------
extern "C" void kernel_launch(void* const* d_in, const int* in_sizes, int n_in,
                              void* d_out, int out_size) {
    const float* img   = (const float*)d_in[0];
    const float* thr   = (const float*)d_in[1];
    const float* gauss = (const float*)d_in[2];

    float* out      = (float*)d_out;
    float* blurred  = out;
    float* grad     = out + 3 * HW_;
    float* orient   = out + 4 * HW_;
    float* thin     = out + 5 * HW_;
    float* thresh   = out + 6 * HW_;
    float* early    = out + 7 * HW_;

    dim3 bgrid(W_ / TILE_X, H_ / TILE_Y, 3);   // 16 x 64 x 3
    blur_f_k<<<bgrid, 256>>>(img, gauss, blurred);

    int blocks1 = (HW_ / 4 + 255) / 256;        // 4096
    sobel_k<<<blocks1, 256>>>(blurred, thr, grad, orient, early);
    nms_k<<<blocks1, 256>>>(grad, orient, thr, thin, thresh);
}